// round 8
// baseline (speedup 1.0000x reference)
#include <cuda_runtime.h>
#include <math.h>

#define Bsz 64
#define Tsz 2000
#define Esz 512
#define Rsz 1024
#define Asz 512
#define Msz 8
#define KS 16
#define NMLPBLK 128              // 8 ntiles x 16 k-splits
#define TSPLIT 20
#define TCHUNK (Tsz / TSPLIT)    // 100
#define HCHUNK (TCHUNK / 2)      // 50
#define NPART (TSPLIT * 2)       // 40 partial slots per batch
#define NBLK (TSPLIT * Bsz)      // 1280 blocks total

// ---------------- scratch -----------------------------------------------------
__device__ float g_part1[KS * Bsz * Asz];
__device__ float g_part2[KS * Bsz * Asz];
__device__ float g_cpart[NPART * Bsz * Esz];
__device__ float g_esum[TSPLIT * Bsz];
__device__ float g_wmix[Bsz * Msz];
__device__ float g_loc[Bsz * Msz];
__device__ float g_scale[Bsz * Msz];
__device__ int   g_ctr[Bsz];     // per-batch ctx completion counters (self-reset)
__device__ int   g_bar1;         // MLP grid barrier 1 (blocks 0..127)
__device__ int   g_bar2;         // MLP grid barrier 2
__device__ int   g_headctr;     // head completion counter (64 blocks)
__device__ int   g_mlp_done;    // flag: MLP outputs ready
__device__ int   g_done;        // global exit counter; last block resets all

// ================= ONE persistent kernel: MLP + prefetch + ctx =================
// grid NBLK x 256. Block bid: b = bid & 63, s = bid >> 6 (ctx task).
// Blocks 0..127 additionally run the MLP (ntile = bid&7, ks = bid>>3).
__global__ void __launch_bounds__(256)
fused_all_kernel(const float* __restrict__ ash,  const float* __restrict__ W1,
                 const float* __restrict__ b1,   const float* __restrict__ W2,
                 const float* __restrict__ Wlin, const float* __restrict__ blin,
                 const float* __restrict__ prev, const float* __restrict__ mem,
                 const unsigned char* __restrict__ mask,
                 float* __restrict__ out_w, float* __restrict__ out_ctx,
                 float* __restrict__ out_loc) {
    __shared__ float As[64][33];
    __shared__ float Ws[64][33];
    __shared__ float sx[Asz];
    __shared__ float ys[24];
    __shared__ float ex[TCHUNK];
    __shared__ float swm[Msz], sl[Msz], ss[Msz];
    __shared__ float red[8];

    const int bid = blockIdx.x;
    const int tid = threadIdx.x;
    const int lane = tid & 31, wrp = tid >> 5;

    // ctx task assignment
    const int b = bid & 63;
    const int s = bid >> 6;          // 0..19
    const int t0 = s * TCHUNK;

    if (bid < NMLPBLK) {
        // ================= MLP path =================
        const int tx = tid & 15, ty = tid >> 4;
        const int ntile = bid & 7;
        const int ks = bid >> 3;
        const int nbase = ntile * 64;

        // ---- stage 1: part1[ks] = tanh(ash) @ W1^T
        {
            const int k0 = ks * (Rsz / KS);
            float acc[4][4] = {};
            for (int kk = 0; kk < Rsz / KS; kk += 32) {
                const int kc = k0 + kk + lane;
#pragma unroll
                for (int r = wrp; r < 64; r += 8) {
                    As[r][lane] = tanhf(ash[r * Rsz + kc]);
                    Ws[r][lane] = W1[(nbase + r) * Rsz + kc];
                }
                __syncthreads();
#pragma unroll
                for (int k = 0; k < 32; k++) {
                    float a[4], w[4];
#pragma unroll
                    for (int i = 0; i < 4; i++) a[i] = As[ty * 4 + i][k];
#pragma unroll
                    for (int j = 0; j < 4; j++) w[j] = Ws[tx * 4 + j][k];
#pragma unroll
                    for (int i = 0; i < 4; i++)
#pragma unroll
                        for (int j = 0; j < 4; j++) acc[i][j] = fmaf(a[i], w[j], acc[i][j]);
                }
                __syncthreads();
            }
#pragma unroll
            for (int i = 0; i < 4; i++)
#pragma unroll
                for (int j = 0; j < 4; j++)
                    g_part1[(ks * 64 + ty * 4 + i) * Asz + nbase + tx * 4 + j] = acc[i][j];
        }

        // ---- grid barrier 1 (blocks 0..127)
        __threadfence();
        __syncthreads();
        if (tid == 0) {
            atomicAdd(&g_bar1, 1);
            while (*(volatile int*)&g_bar1 < NMLPBLK) { }
        }
        __syncthreads();
        __threadfence();

        // ---- stage 2: part2[ks] = (sum part1 + b1) @ W2^T
        {
            const int kc = ks * (Asz / KS) + lane;
            float acc[4][4] = {};
            const float bb = b1[kc];
#pragma unroll
            for (int r = wrp; r < 64; r += 8) {
                float sv = bb;
#pragma unroll
                for (int p = 0; p < KS; p++) sv += g_part1[(p * 64 + r) * Asz + kc];
                As[r][lane] = sv;
                Ws[r][lane] = W2[(nbase + r) * Asz + kc];
            }
            __syncthreads();
#pragma unroll
            for (int k = 0; k < 32; k++) {
                float a[4], w[4];
#pragma unroll
                for (int i = 0; i < 4; i++) a[i] = As[ty * 4 + i][k];
#pragma unroll
                for (int j = 0; j < 4; j++) w[j] = Ws[tx * 4 + j][k];
#pragma unroll
                for (int i = 0; i < 4; i++)
#pragma unroll
                    for (int j = 0; j < 4; j++) acc[i][j] = fmaf(a[i], w[j], acc[i][j]);
            }
            __syncthreads();
#pragma unroll
            for (int i = 0; i < 4; i++)
#pragma unroll
                for (int j = 0; j < 4; j++)
                    g_part2[(ks * 64 + ty * 4 + i) * Asz + nbase + tx * 4 + j] = acc[i][j];
        }

        // ---- grid barrier 2
        __threadfence();
        __syncthreads();
        if (tid == 0) {
            atomicAdd(&g_bar2, 1);
            while (*(volatile int*)&g_bar2 < NMLPBLK) { }
        }
        __syncthreads();
        __threadfence();

        // ---- head (blocks 0..63, one per batch)
        if (bid < Bsz) {
            const int hb = bid;
            for (int i = tid; i < Asz; i += 256) {
                float sv = 0.0f;
#pragma unroll
                for (int p = 0; p < KS; p++) sv += g_part2[(p * 64 + hb) * Asz + i];
                sx[i] = tanhf(sv);
            }
            __syncthreads();

            for (int o = wrp; o < 24; o += 8) {
                float sv = 0.0f;
                const float* wr = Wlin + o * Asz;
                for (int k = lane; k < Asz; k += 32) sv = fmaf(sx[k], wr[k], sv);
#pragma unroll
                for (int off = 16; off > 0; off >>= 1)
                    sv += __shfl_down_sync(0xffffffffu, sv, off);
                if (lane == 0) ys[o] = sv + blin[o];
            }
            __syncthreads();

            if (tid < Msz) {
                const int m = tid;
                float wmix = 1.0f / (1.0f + expf(-ys[m]));
                float loc = prev[hb * Msz + m] + 1.0f / (1.0f + expf(-ys[Msz + m]));
                float scl = 1.0f / (1.0f + expf(-ys[2 * Msz + m])) * 2.0f + 1.0f;
                g_wmix[hb * Msz + m] = wmix;
                g_loc[hb * Msz + m] = loc;
                g_scale[hb * Msz + m] = scl;
                out_loc[hb * Msz + m] = loc;
            }
            __threadfence();
            __syncthreads();
            if (tid == 0) {
                int old = atomicAdd(&g_headctr, 1);
                if (old == Bsz - 1) {
                    __threadfence();
                    *(volatile int*)&g_mlp_done = 1;
                }
            }
        }
    } else {
        // ================= prefetch path (blocks 128..1279) =================
        // Pull this block's ctx region into L2 (__ldcg = keep) while the MLP
        // runs; stop the moment the MLP done-flag flips.
        const float4* base = (const float4*)(mem + (size_t)b * Tsz * Esz)
                             + (size_t)t0 * (Esz / 4);
        float dummy = 0.0f;
        // region = TCHUNK*128 = 12800 float4 = 50 sweeps of 256 threads
        for (int cc = 0; cc < 50; cc += 5) {
            if (*(volatile int*)&g_mlp_done) break;
#pragma unroll
            for (int c = cc; c < cc + 5; c++) {
                float4 v = __ldcg(base + c * 256 + tid);
                dummy += v.x + v.y + v.z + v.w;
            }
        }
        asm volatile("" :: "f"(dummy));   // keep the prefetch loads alive
    }

    // ---- all blocks: wait for MLP outputs ----
    if (tid == 0) {
        while (*(volatile int*)&g_mlp_done == 0) __nanosleep(64);
    }
    __syncthreads();
    __threadfence();

    // ================= ctx phase (all 1280 blocks; R6 shape) =================
    if (tid < Msz) {
        swm[tid] = g_wmix[b * Msz + tid];
        sl[tid]  = g_loc[b * Msz + tid];
        ss[tid]  = g_scale[b * Msz + tid];
    }
    __syncthreads();

    // alignment + exp (no max-subtraction: alignment in [0,8], exp safe)
    if (tid < TCHUNK) {
        const int t = t0 + tid;
        float al = 0.0f;
        const float ft = (float)t;
#pragma unroll
        for (int m = 0; m < Msz; m++) {
            float d = sl[m] - ft;
            float sc = ss[m];
            float z = 0.5f * (erff((d + 0.5f) * sc) - erff((d - 0.5f) * sc));
            al = fmaf(z, swm[m], al);
        }
        if (mask[b * Tsz + t]) al = 0.0f;
        float e = __expf(al);
        ex[tid] = e;
        out_w[b * Tsz + t] = e;             // rescaled by the last block
    }
    __syncthreads();

    // block partial exp-sum
    {
        float v = (tid < TCHUNK) ? ex[tid] : 0.0f;
#pragma unroll
        for (int off = 16; off > 0; off >>= 1)
            v += __shfl_xor_sync(0xffffffffu, v, off);
        if (lane == 0) red[wrp] = v;
        __syncthreads();
        if (tid == 0) {
            float S = 0.0f;
#pragma unroll
            for (int w = 0; w < 8; w++) S += red[w];
            g_esum[s * Bsz + b] = S;
        }
    }

    // stream: warps 0-3 take rows [t0,t0+50), warps 4-7 rows [t0+50,t0+100)
    const int half = tid >> 7;
    const int e4 = tid & 127;
    const float4* mrow = (const float4*)(mem + (size_t)b * Tsz * Esz)
                         + (size_t)(t0 + half * HCHUNK) * (Esz / 4) + e4;
    const float* exh = ex + half * HCHUNK;

    float4 acc = make_float4(0.f, 0.f, 0.f, 0.f);
#pragma unroll 4
    for (int i = 0; i < HCHUNK; i++) {
        float w = exh[i];
        float4 v = __ldcs(mrow + i * (Esz / 4));   // evict-first: protect prefetch
        acc.x = fmaf(w, v.x, acc.x);
        acc.y = fmaf(w, v.y, acc.y);
        acc.z = fmaf(w, v.z, acc.z);
        acc.w = fmaf(w, v.w, acc.w);
    }
    ((float4*)g_cpart)[((s * 2 + half) * Bsz + b) * (Esz / 4) + e4] = acc;

    // release then signal
    __threadfence();
    __syncthreads();
    __shared__ int done;
    if (tid == 0) done = atomicAdd(&g_ctr[b], 1);
    __syncthreads();

    if (done == TSPLIT - 1) {
        __threadfence();  // acquire
        float S = 0.0f;
#pragma unroll
        for (int p = 0; p < TSPLIT; p++) S += g_esum[p * Bsz + b];
        const float inv = 1.0f / S;

        if (tid < 128) {
            float4 sum = make_float4(0.f, 0.f, 0.f, 0.f);
#pragma unroll
            for (int p = 0; p < NPART; p++) {
                float4 v = ((const float4*)g_cpart)[(p * Bsz + b) * (Esz / 4) + tid];
                sum.x += v.x; sum.y += v.y; sum.z += v.z; sum.w += v.w;
            }
            sum.x *= inv; sum.y *= inv; sum.z *= inv; sum.w *= inv;
            ((float4*)out_ctx)[b * (Esz / 4) + tid] = sum;
        }

        for (int t = tid; t < Tsz; t += 256)
            out_w[b * Tsz + t] *= inv;

        if (tid == 0) g_ctr[b] = 0;  // reset for next replay
    }

    // ---- global exit: last block resets MLP barriers/flags for next replay ----
    __syncthreads();
    if (tid == 0) {
        __threadfence();
        int old = atomicAdd(&g_done, 1);
        if (old == NBLK - 1) {
            g_bar1 = 0;
            g_bar2 = 0;
            g_headctr = 0;
            g_mlp_done = 0;
            g_done = 0;
            __threadfence();
        }
    }
}

// ---------------- launch --------------------------------------------------------
extern "C" void kernel_launch(void* const* d_in, const int* in_sizes, int n_in,
                              void* d_out, int out_size) {
    const float* ash  = (const float*)d_in[0];
    const float* mem  = (const float*)d_in[1];
    const float* prev = (const float*)d_in[2];
    const unsigned char* mask = (const unsigned char*)d_in[3];
    const float* W1   = (const float*)d_in[4];
    const float* b1   = (const float*)d_in[5];
    const float* W2   = (const float*)d_in[6];
    const float* Wlin = (const float*)d_in[7];
    const float* blin = (const float*)d_in[8];

    float* out     = (float*)d_out;
    float* out_ctx = out;
    float* out_w   = out + Bsz * Esz;
    float* out_loc = out_w + Bsz * Tsz;

    fused_all_kernel<<<NBLK, 256>>>(ash, W1, b1, W2, Wlin, blin, prev,
                                    mem, mask, out_w, out_ctx, out_loc);
}